// round 14
// baseline (speedup 1.0000x reference)
#include <cuda_runtime.h>
#include <cuda_fp16.h>
#include <cstdint>

#define N_NODES 50000
#define F_DIM 512
#define C_DIM 64
#define O_DIM 256
#define GRID_MAX 152
#define NT 128
#define NTILES ((N_NODES + NT - 1) / NT)   // 391
#define THREADS 512

typedef unsigned long long ull;

// ---- smem byte offsets ----
#define OFF_WB   0          // Wp frags fp16 hi/lo: 2 x 65536 = 131072
#define OFF_XU   131072     // 64KB union: Phase A A-frags / Phase C xh(32KB)+xl(32KB)
#define OFF_S    196608     // 32KB union: logits fp32 XOR layout -> s-frags sh(16KB)+sl(16KB)
#define OFF_BP   229376     // 256B
#define SMEM_TOTAL 229664

// Scratch (static device arrays; no allocation)
__device__ float g_Mpart[GRID_MAX * C_DIM * F_DIM];
__device__ float g_cspart[GRID_MAX * C_DIM];
__device__ float g_M[C_DIM * F_DIM];
__device__ float g_cs[C_DIM];
__device__ float g_pooled[C_DIM * F_DIM];
__device__ unsigned g_bar;

static __device__ __forceinline__ void mma16816(float* d, const uint32_t* a, uint32_t b0, uint32_t b1) {
    asm volatile(
        "mma.sync.aligned.m16n8k16.row.col.f32.f16.f16.f32 "
        "{%0,%1,%2,%3}, {%4,%5,%6,%7}, {%8,%9}, {%0,%1,%2,%3};"
        : "+f"(d[0]), "+f"(d[1]), "+f"(d[2]), "+f"(d[3])
        : "r"(a[0]), "r"(a[1]), "r"(a[2]), "r"(a[3]), "r"(b0), "r"(b1));
}

// Grid-wide barrier: all CTAs resident (grid == #SMs, occ 1). Monotonic counter.
static __device__ __forceinline__ void grid_sync() {
    __syncthreads();
    __threadfence();
    if (threadIdx.x == 0) {
        unsigned old = atomicAdd(&g_bar, 1u);
        unsigned target = old - (old % gridDim.x) + gridDim.x;
        while (*(volatile unsigned*)&g_bar < target) __nanosleep(64);
        __threadfence();
    }
    __syncthreads();
}

__global__ __launch_bounds__(THREADS, 1) void k1_fused(
    const float* __restrict__ x, const float* __restrict__ Wp, const float* __restrict__ bp,
    const float* __restrict__ We, const float* __restrict__ be,
    const float* __restrict__ Wo, const float* __restrict__ bo,
    float* __restrict__ out)
{
    extern __shared__ char smc[];
    float4* ss4 = (float4*)(smc + OFF_S);
    float*  sSf = (float*)(smc + OFF_S);
    float*  bpS = (float*)(smc + OFF_BP);

    const int tid = threadIdx.x;
    const int G = gridDim.x;

    // ---- one-time init: Wp -> fp16 hi/lo B-fragment layout; bp stage ----
    for (int idx = tid; idx < F_DIM * C_DIM; idx += THREADS) {
        int k = idx >> 6, c = idx & 63;
        float wv = Wp[idx];
        __half hh = __float2half_rn(wv);
        __half hl = __float2half_rn(wv - __half2float(hh));
        int ks = k >> 4, kk = k & 15, kp = kk >> 1, par = kk & 1;
        int ct = c >> 3, col = c & 7;
        int reg = kp >> 2, lane = col * 4 + (kp & 3);
        int off = (((ks) * 8 + ct) * 32 + lane) * 8 + reg * 4 + par * 2;
        *(__half*)(smc + OFF_WB + off) = hh;
        *(__half*)(smc + OFF_WB + 65536 + off) = hl;
    }
    if (tid < 64) bpS[tid] = bp[tid];
    __syncthreads();

    const int w = tid >> 5, lane = tid & 31;
    const int nt = w >> 1, chalf = w & 1;          // Phase A mma: warp = (n-tile, c-half)
    const int cq = tid & 15, ng = tid >> 4;        // softmax: 4 clusters x 4 nodes
    const int ctile = w & 3, fgrp = w >> 2;        // Phase C mma: warp = (c-tile, f-group)

    float accM[4][4][4];                           // [f-chunk][ftile][reg]
    #pragma unroll
    for (int a = 0; a < 4; ++a)
        #pragma unroll
        for (int b = 0; b < 4; ++b)
            #pragma unroll
            for (int r = 0; r < 4; ++r) accM[a][b][r] = 0.f;
    float cs0 = 0.f, cs1 = 0.f, cs2 = 0.f, cs3 = 0.f;

    for (int tile = blockIdx.x; tile < NTILES; tile += G) {
        const int node0 = tile * NT;

        // ===== Phase A: logits = xh @ (Wh + Wl) via mma.sync (R12, verified) =====
        float accA[4][4];
        #pragma unroll
        for (int t = 0; t < 4; ++t)
            #pragma unroll
            for (int r = 0; r < 4; ++r) accA[t][r] = 0.f;

        #pragma unroll 1
        for (int cc = 0; cc < 2; ++cc) {
            __syncthreads();
            #pragma unroll
            for (int it = 0; it < 16; ++it) {
                int j = tid + it * THREADS;        // 0..8191
                int kq = j & 63, n = j >> 6;
                int node = node0 + n;
                float4 v = make_float4(0.f, 0.f, 0.f, 0.f);
                if (node < N_NODES)
                    v = *(const float4*)(x + (size_t)node * F_DIM + cc * 256 + kq * 4);
                uint32_t h01, h23;
                { __half2 t2 = __floats2half2_rn(v.x, v.y); h01 = *(uint32_t*)&t2; }
                { __half2 t2 = __floats2half2_rn(v.z, v.w); h23 = *(uint32_t*)&t2; }
                int ksl = kq >> 2, kqq = kq & 3;
                int ntn = n >> 4, rr = n & 15, rlow = rr & 7, rhi = rr >> 3;
                int p0 = kqq * 2;
                int lane0 = rlow * 4 + (p0 & 3);
                int lane1 = rlow * 4 + ((p0 + 1) & 3);
                int reg0 = ((p0 >> 2) << 1) | rhi;
                *(uint32_t*)(smc + OFF_XU + ((ksl * 8 + ntn) * 32 + lane0) * 16 + reg0 * 4) = h01;
                *(uint32_t*)(smc + OFF_XU + ((ksl * 8 + ntn) * 32 + lane1) * 16 + reg0 * 4) = h23;
            }
            __syncthreads();

            #pragma unroll 4
            for (int ks = 0; ks < 16; ++ks) {
                uint4 av = *(const uint4*)(smc + OFF_XU + ((ks * 8 + nt) * 32 + lane) * 16);
                const int ksg = cc * 16 + ks;
                #pragma unroll
                for (int seg = 0; seg < 2; ++seg) {
                    #pragma unroll
                    for (int t = 0; t < 4; ++t) {
                        int ct = chalf * 4 + t;
                        uint2 bv = *(const uint2*)(smc + OFF_WB + seg * 65536 +
                                                   ((ksg * 8 + ct) * 32 + lane) * 8);
                        mma16816(accA[t], (const uint32_t*)&av, bv.x, bv.y);
                    }
                }
            }
        }

        // write logits to sS (fp32 XOR layout)
        __syncthreads();
        {
            const int r0 = nt * 16 + (lane >> 2);
            const int r1 = r0 + 8;
            #pragma unroll
            for (int t = 0; t < 4; ++t) {
                int c = chalf * 32 + t * 8 + (lane & 3) * 2;
                int c4 = c >> 2, ci = c & 3;
                float* p0 = sSf + r0 * 64 + (c4 ^ (r0 & 15)) * 4 + ci;
                float* p1 = sSf + r1 * 64 + (c4 ^ (r1 & 15)) * 4 + ci;
                p0[0] = accA[t][0]; p0[1] = accA[t][1];
                p1[0] = accA[t][2]; p1[1] = accA[t][3];
            }
        }
        __syncthreads();

        // ===== Phase B: softmax -> s held in regs, then scattered as A-frags =====
        float4 svr[4];
        #pragma unroll
        for (int i = 0; i < 4; ++i) {
            const int n = ng * 4 + i;
            float4 lv = ss4[n * 16 + (cq ^ (n & 15))];
            float l0 = lv.x + bpS[cq * 4 + 0];
            float l1 = lv.y + bpS[cq * 4 + 1];
            float l2 = lv.z + bpS[cq * 4 + 2];
            float l3 = lv.w + bpS[cq * 4 + 3];
            float m = fmaxf(fmaxf(l0, l1), fmaxf(l2, l3));
            #pragma unroll
            for (int d = 1; d < 16; d <<= 1) m = fmaxf(m, __shfl_xor_sync(0xffffffffu, m, d));
            float e0 = __expf(l0 - m), e1 = __expf(l1 - m), e2 = __expf(l2 - m), e3 = __expf(l3 - m);
            float s = e0 + e1 + e2 + e3;
            #pragma unroll
            for (int d = 1; d < 16; d <<= 1) s += __shfl_xor_sync(0xffffffffu, s, d);
            float r = __frcp_rn(s);
            if (node0 + n >= N_NODES) r = 0.f;
            svr[i] = make_float4(e0 * r, e1 * r, e2 * r, e3 * r);
            cs0 += svr[i].x; cs1 += svr[i].y; cs2 += svr[i].z; cs3 += svr[i].w;
        }
        __syncthreads();       // everyone done READING logits before overwrite

        // scatter s as fp16 hi/lo A-fragments: sh @ OFF_S, sl @ OFF_S+16384
        #pragma unroll
        for (int i = 0; i < 4; ++i) {
            const int n = ng * 4 + i;
            const int kstep = n >> 4, kcol = n & 15;
            const int kpair = kcol >> 1, par = kcol & 1;
            const float sv[4] = { svr[i].x, svr[i].y, svr[i].z, svr[i].w };
            #pragma unroll
            for (int ci = 0; ci < 4; ++ci) {
                int c = cq * 4 + ci;
                int row = c & 15, ct2 = c >> 4;
                int lane2 = (row & 7) * 4 + (kpair & 3);
                int reg = ((kpair >> 2) << 1) | (row >> 3);
                int off = ((ct2 * 8 + kstep) * 32 + lane2) * 16 + reg * 4 + par * 2;
                __half sh_ = __float2half_rn(sv[ci]);
                __half sl_ = __float2half_rn(sv[ci] - __half2float(sh_));
                *(__half*)(smc + OFF_S + off) = sh_;
                *(__half*)(smc + OFF_S + 16384 + off) = sl_;
            }
        }

        // ===== Phase C: M += s^T x via mma.sync, 4 f-chunks, 3 hi/lo terms =====
        #pragma unroll
        for (int fc = 0; fc < 4; ++fc) {
            __syncthreads();   // also covers s-frag visibility on fc==0
            // stage x B-frags for this 128-f chunk: node-pairs -> half2 regs
            #pragma unroll
            for (int it = 0; it < 4; ++it) {
                int j = tid + it * THREADS;        // 0..2047
                int f4i = j & 31, np = j >> 5;     // f-quad, node-pair
                int na = node0 + 2 * np, nb = na + 1;
                float4 v0 = make_float4(0.f, 0.f, 0.f, 0.f);
                float4 v1 = make_float4(0.f, 0.f, 0.f, 0.f);
                if (na < N_NODES) v0 = *(const float4*)(x + (size_t)na * F_DIM + fc * 128 + f4i * 4);
                if (nb < N_NODES) v1 = *(const float4*)(x + (size_t)nb * F_DIM + fc * 128 + f4i * 4);
                const int kstep = np >> 3, kpl = np & 7;
                const int reg = kpl >> 2, lb = kpl & 3;
                const float a0[4] = { v0.x, v0.y, v0.z, v0.w };
                const float a1[4] = { v1.x, v1.y, v1.z, v1.w };
                #pragma unroll
                for (int f = 0; f < 4; ++f) {
                    int fl = f4i * 4 + f;
                    int lane2 = (fl & 7) * 4 + lb;
                    int ftile = fl >> 3;
                    uint32_t off = ((ftile * 8 + kstep) * 32 + lane2) * 8 + reg * 4;
                    __half2 hh = __floats2half2_rn(a0[f], a1[f]);
                    float2 hf = __half22float2(hh);
                    __half2 hl = __floats2half2_rn(a0[f] - hf.x, a1[f] - hf.y);
                    *(uint32_t*)(smc + OFF_XU + off) = *(uint32_t*)&hh;
                    *(uint32_t*)(smc + OFF_XU + 32768 + off) = *(uint32_t*)&hl;
                }
            }
            __syncthreads();

            #pragma unroll
            for (int ks = 0; ks < 8; ++ks) {
                uint4 ash = *(const uint4*)(smc + OFF_S + ((ctile * 8 + ks) * 32 + lane) * 16);
                uint4 asl = *(const uint4*)(smc + OFF_S + 16384 + ((ctile * 8 + ks) * 32 + lane) * 16);
                #pragma unroll
                for (int t = 0; t < 4; ++t) {
                    int ftile = fgrp * 4 + t;
                    uint2 bh = *(const uint2*)(smc + OFF_XU + ((ftile * 8 + ks) * 32 + lane) * 8);
                    uint2 bl = *(const uint2*)(smc + OFF_XU + 32768 + ((ftile * 8 + ks) * 32 + lane) * 8);
                    mma16816(accM[fc][t], (const uint32_t*)&ash, bh.x, bh.y);   // sh*xh
                    mma16816(accM[fc][t], (const uint32_t*)&ash, bl.x, bl.y);   // sh*xl
                    mma16816(accM[fc][t], (const uint32_t*)&asl, bh.x, bh.y);   // sl*xh
                }
            }
        }
        __syncthreads();       // frag buffers reused next tile
    }

    // ---- per-block partial M from C-fragments ----
    {
        float* mp = g_Mpart + (size_t)blockIdx.x * (C_DIM * F_DIM);
        #pragma unroll
        for (int fc = 0; fc < 4; ++fc)
            #pragma unroll
            for (int t = 0; t < 4; ++t) {
                int cb2 = ctile * 16 + (lane >> 2);
                int fb = fc * 128 + (fgrp * 4 + t) * 8 + (lane & 3) * 2;
                *(float2*)(mp + cb2 * F_DIM + fb) = make_float2(accM[fc][t][0], accM[fc][t][1]);
                *(float2*)(mp + (cb2 + 8) * F_DIM + fb) = make_float2(accM[fc][t][2], accM[fc][t][3]);
            }
    }
    // ---- per-block partial colsum(s) (scratch in dead s region) ----
    {
        float* csS = (float*)(smc + OFF_S);
        __syncthreads();
        if (tid < 64) csS[tid] = 0.f;
        __syncthreads();
        atomicAdd(&csS[cq * 4 + 0], cs0);
        atomicAdd(&csS[cq * 4 + 1], cs1);
        atomicAdd(&csS[cq * 4 + 2], cs2);
        atomicAdd(&csS[cq * 4 + 3], cs3);
        __syncthreads();
        if (tid < 64) g_cspart[blockIdx.x * 64 + tid] = csS[tid];
    }

    // ================= In-kernel epilogue (grid-synchronized) =================
    grid_sync();

    {
        unsigned idx = blockIdx.x * (unsigned)THREADS + (unsigned)tid;
        if (idx < C_DIM * F_DIM) {
            float s = 0.f;
            #pragma unroll 4
            for (int b = 0; b < G; ++b) s += g_Mpart[(size_t)b * (C_DIM * F_DIM) + idx];
            g_M[idx] = s;
        }
        if (blockIdx.x == 64 && tid < C_DIM) {
            float s = 0.f;
            #pragma unroll 4
            for (int b = 0; b < G; ++b) s += g_cspart[b * C_DIM + tid];
            g_cs[tid] = s;
        }
    }

    grid_sync();

    // pooled = M @ We + cs (x) be : blocks 0..15, 4 clusters each, f = tid
    if (blockIdx.x < 16) {
        const int f = tid;
        const int cb = blockIdx.x * 4;
        const float bef = be[f];
        float a0 = g_cs[cb + 0] * bef;
        float a1 = g_cs[cb + 1] * bef;
        float a2 = g_cs[cb + 2] * bef;
        float a3 = g_cs[cb + 3] * bef;
        #pragma unroll 8
        for (int k = 0; k < F_DIM; ++k) {
            float wv = We[(size_t)k * F_DIM + f];
            a0 += g_M[(cb + 0) * F_DIM + k] * wv;
            a1 += g_M[(cb + 1) * F_DIM + k] * wv;
            a2 += g_M[(cb + 2) * F_DIM + k] * wv;
            a3 += g_M[(cb + 3) * F_DIM + k] * wv;
        }
        g_pooled[(cb + 0) * F_DIM + f] = a0;
        g_pooled[(cb + 1) * F_DIM + f] = a1;
        g_pooled[(cb + 2) * F_DIM + f] = a2;
        g_pooled[(cb + 3) * F_DIM + f] = a3;
    }

    grid_sync();

    // out = pooled @ Wo + bo : blocks 0..63 (one cluster each), k split 2 ways
    if (blockIdx.x < 64) {
        const int o = tid & 255, q = tid >> 8, c = blockIdx.x;
        float a = 0.f;
        const int kbeg = q * 256;
        #pragma unroll 8
        for (int k = kbeg; k < kbeg + 256; ++k)
            a += g_pooled[c * F_DIM + k] * Wo[(size_t)k * O_DIM + o];
        float* rsm = (float*)(smc + OFF_XU);
        rsm[q * 256 + o] = a;
        __syncthreads();
        if (q == 0) out[c * O_DIM + o] = rsm[o] + rsm[256 + o] + bo[o];
    }
}

extern "C" void kernel_launch(void* const* d_in, const int* in_sizes, int n_in,
                              void* d_out, int out_size) {
    const float* x  = (const float*)d_in[0];
    // d_in[1] = edge_index (int64), d_in[2] = batch (int64): unused by the output
    const float* Wp = (const float*)d_in[3];
    const float* bp = (const float*)d_in[4];
    const float* We = (const float*)d_in[5];
    const float* be = (const float*)d_in[6];
    const float* Wo = (const float*)d_in[7];
    const float* bo = (const float*)d_in[8];
    float* out = (float*)d_out;

    int dev = 0;
    cudaGetDevice(&dev);
    int smc_n = GRID_MAX;
    cudaDeviceGetAttribute(&smc_n, cudaDevAttrMultiProcessorCount, dev);
    int G = smc_n < GRID_MAX ? smc_n : GRID_MAX;

    cudaFuncSetAttribute(k1_fused, cudaFuncAttributeMaxDynamicSharedMemorySize, SMEM_TOTAL);
    k1_fused<<<G, THREADS, SMEM_TOTAL>>>(x, Wp, bp, We, be, Wo, bo, out);
}

// round 15
// speedup vs baseline: 1.1908x; 1.1908x over previous
#include <cuda_runtime.h>
#include <cuda_fp16.h>
#include <cstdint>

#define N_NODES 50000
#define F_DIM 512
#define C_DIM 64
#define O_DIM 256
#define GRID_MAX 152
#define NT 128
#define NTILES ((N_NODES + NT - 1) / NT)   // 391
#define THREADS 512

typedef unsigned long long ull;

// ---- smem byte offsets ----
#define OFF_WB 0            // Wp-hi frags fp16: 64KB
#define OFF_XA 65536        // A-frag quarter (next tile): 32KB
#define OFF_XC 98304        // Phase C x chunk fp32 (current tile): 64KB
#define OFF_S  163840       // logits/s fp32 XOR layout: 32KB
#define OFF_BP 196608       // 256B
#define SMEM_TOTAL 196864

// Scratch (static device arrays; no allocation)
__device__ uint2 g_WpLoFrag[8192];         // Wp-lo frags, L2-resident
__device__ float g_Mpart[GRID_MAX * C_DIM * F_DIM];
__device__ float g_cspart[GRID_MAX * C_DIM];
__device__ float g_M[C_DIM * F_DIM];
__device__ float g_cs[C_DIM];
__device__ float g_pooled[C_DIM * F_DIM];
__device__ unsigned g_bar;

static __device__ __forceinline__ ull pack2(float lo, float hi) {
    ull r; asm("mov.b64 %0, {%1,%2};" : "=l"(r) : "f"(lo), "f"(hi)); return r;
}
static __device__ __forceinline__ void unpack2(ull v, float& lo, float& hi) {
    asm("mov.b64 {%0,%1}, %2;" : "=f"(lo), "=f"(hi) : "l"(v));
}
static __device__ __forceinline__ ull fma2(ull a, ull b, ull c) {
    ull d; asm("fma.rn.f32x2 %0, %1, %2, %3;" : "=l"(d) : "l"(a), "l"(b), "l"(c)); return d;
}
static __device__ __forceinline__ void mma16816(float* d, const uint32_t* a, uint32_t b0, uint32_t b1) {
    asm volatile(
        "mma.sync.aligned.m16n8k16.row.col.f32.f16.f16.f32 "
        "{%0,%1,%2,%3}, {%4,%5,%6,%7}, {%8,%9}, {%0,%1,%2,%3};"
        : "+f"(d[0]), "+f"(d[1]), "+f"(d[2]), "+f"(d[3])
        : "r"(a[0]), "r"(a[1]), "r"(a[2]), "r"(a[3]), "r"(b0), "r"(b1));
}

// Grid-wide barrier: all CTAs resident (grid == #SMs, occ 1). Monotonic counter.
static __device__ __forceinline__ void grid_sync() {
    __syncthreads();
    __threadfence();
    if (threadIdx.x == 0) {
        unsigned old = atomicAdd(&g_bar, 1u);
        unsigned target = old - (old % gridDim.x) + gridDim.x;
        while (*(volatile unsigned*)&g_bar < target) __nanosleep(64);
        __threadfence();
    }
    __syncthreads();
}

// Stage one 128-k quarter of next tile's x as fp16 A-fragments (R12 math).
static __device__ __forceinline__ void stage_A(
    char* smc, const float* __restrict__ x, int node0n, int q, int tid)
{
    #pragma unroll
    for (int it = 0; it < 8; ++it) {
        int j = tid + it * THREADS;            // 0..4095
        int kqd = j & 31, n = j >> 5;
        int node = node0n + n;
        float4 v = make_float4(0.f, 0.f, 0.f, 0.f);
        if (node < N_NODES)
            v = *(const float4*)(x + (size_t)node * F_DIM + q * 128 + kqd * 4);
        uint32_t h01, h23;
        { __half2 t2 = __floats2half2_rn(v.x, v.y); h01 = *(uint32_t*)&t2; }
        { __half2 t2 = __floats2half2_rn(v.z, v.w); h23 = *(uint32_t*)&t2; }
        int ksl = kqd >> 2, kqq = kqd & 3;
        int ntn = n >> 4, rr = n & 15, rlow = rr & 7, rhi = rr >> 3;
        int p0 = kqq * 2;
        int lane0 = rlow * 4 + (p0 & 3);
        int lane1 = rlow * 4 + ((p0 + 1) & 3);
        int reg0 = ((p0 >> 2) << 1) | rhi;
        *(uint32_t*)(smc + OFF_XA + ((ksl * 8 + ntn) * 32 + lane0) * 16 + reg0 * 4) = h01;
        *(uint32_t*)(smc + OFF_XA + ((ksl * 8 + ntn) * 32 + lane1) * 16 + reg0 * 4) = h23;
    }
}

// One ks-step of the logits mma for quarter q (hi from smem, lo from global).
static __device__ __forceinline__ void mma_A_step(
    char* smc, float accA[4][4], int ks, int q, int nt, int chalf, int lane)
{
    uint4 av = *(const uint4*)(smc + OFF_XA + ((ks * 8 + nt) * 32 + lane) * 16);
    int ksg = q * 8 + ks;
    #pragma unroll
    for (int t2 = 0; t2 < 4; ++t2) {
        int ct = chalf * 4 + t2;
        uint2 bh = *(const uint2*)(smc + OFF_WB + ((ksg * 8 + ct) * 32 + lane) * 8);
        uint2 bl = g_WpLoFrag[(ksg * 8 + ct) * 32 + lane];
        mma16816(accA[t2], (const uint32_t*)&av, bh.x, bh.y);
        mma16816(accA[t2], (const uint32_t*)&av, bl.x, bl.y);
    }
}

__global__ __launch_bounds__(THREADS, 1) void k1_fused(
    const float* __restrict__ x, const float* __restrict__ Wp, const float* __restrict__ bp,
    const float* __restrict__ We, const float* __restrict__ be,
    const float* __restrict__ Wo, const float* __restrict__ bo,
    float* __restrict__ out)
{
    extern __shared__ char smc[];
    float4* xs4 = (float4*)(smc + OFF_XC);
    float4* ss4 = (float4*)(smc + OFF_S);
    float*  sSf = (float*)(smc + OFF_S);
    float*  bpS = (float*)(smc + OFF_BP);

    const int tid = threadIdx.x;
    const int G = gridDim.x;

    // ---- one-time init: Wp -> fp16 hi frags (smem) + lo frags (global); bp ----
    for (int idx = tid; idx < F_DIM * C_DIM; idx += THREADS) {
        int k = idx >> 6, c = idx & 63;
        float wv = Wp[idx];
        __half hh = __float2half_rn(wv);
        __half hl = __float2half_rn(wv - __half2float(hh));
        int ks = k >> 4, kk = k & 15, kp = kk >> 1, par = kk & 1;
        int ct = c >> 3, col = c & 7;
        int reg = kp >> 2, lane = col * 4 + (kp & 3);
        int off = (((ks) * 8 + ct) * 32 + lane) * 8 + reg * 4 + par * 2;
        *(__half*)(smc + OFF_WB + off) = hh;
        *(__half*)((char*)g_WpLoFrag + off) = hl;
    }
    if (tid < 64) bpS[tid] = bp[tid];
    __syncthreads();

    const int w = tid >> 5, lane = tid & 31;
    const int nt = w >> 1, chalf = w & 1;          // mma: warp = (n-tile, c-half)
    const int cq = tid & 15, ng = tid >> 4;        // softmax: 4 clusters x 4 nodes
    const int f4 = lane;                           // Phase C: warp = c-quad, lane = f-quad

    ull Macc[4][4][2];
    #pragma unroll
    for (int a = 0; a < 4; ++a)
        #pragma unroll
        for (int b = 0; b < 4; ++b) { Macc[a][b][0] = 0ull; Macc[a][b][1] = 0ull; }
    float cs0 = 0.f, cs1 = 0.f, cs2 = 0.f, cs3 = 0.f;
    float accA[4][4];

    const int tile0 = blockIdx.x;

    // ===== Prologue: Phase A + B for first tile =====
    {
        #pragma unroll
        for (int t = 0; t < 4; ++t)
            #pragma unroll
            for (int r = 0; r < 4; ++r) accA[t][r] = 0.f;
        #pragma unroll 1
        for (int q = 0; q < 4; ++q) {
            __syncthreads();
            stage_A(smc, x, tile0 * NT, q, tid);
            __syncthreads();
            #pragma unroll
            for (int ks = 0; ks < 8; ++ks) mma_A_step(smc, accA, ks, q, nt, chalf, lane);
        }
        __syncthreads();
        // logits -> S (XOR layout)
        {
            const int r0 = nt * 16 + (lane >> 2);
            const int r1 = r0 + 8;
            #pragma unroll
            for (int t = 0; t < 4; ++t) {
                int c = chalf * 32 + t * 8 + (lane & 3) * 2;
                int c4 = c >> 2, ci = c & 3;
                float* p0 = sSf + r0 * 64 + (c4 ^ (r0 & 15)) * 4 + ci;
                float* p1 = sSf + r1 * 64 + (c4 ^ (r1 & 15)) * 4 + ci;
                p0[0] = accA[t][0]; p0[1] = accA[t][1];
                p1[0] = accA[t][2]; p1[1] = accA[t][3];
            }
        }
        __syncthreads();
        // softmax in place
        #pragma unroll
        for (int i = 0; i < 4; ++i) {
            const int n = ng * 4 + i;
            float4 lv = ss4[n * 16 + (cq ^ (n & 15))];
            float l0 = lv.x + bpS[cq * 4 + 0];
            float l1 = lv.y + bpS[cq * 4 + 1];
            float l2 = lv.z + bpS[cq * 4 + 2];
            float l3 = lv.w + bpS[cq * 4 + 3];
            float m = fmaxf(fmaxf(l0, l1), fmaxf(l2, l3));
            #pragma unroll
            for (int d = 1; d < 16; d <<= 1) m = fmaxf(m, __shfl_xor_sync(0xffffffffu, m, d));
            float e0 = __expf(l0 - m), e1 = __expf(l1 - m), e2 = __expf(l2 - m), e3 = __expf(l3 - m);
            float s = e0 + e1 + e2 + e3;
            #pragma unroll
            for (int d = 1; d < 16; d <<= 1) s += __shfl_xor_sync(0xffffffffu, s, d);
            float r = __frcp_rn(s);
            if (tile0 * NT + n >= N_NODES) r = 0.f;
            float4 sv = make_float4(e0 * r, e1 * r, e2 * r, e3 * r);
            cs0 += sv.x; cs1 += sv.y; cs2 += sv.z; cs3 += sv.w;
            ss4[n * 16 + (cq ^ (n & 15))] = sv;
        }
    }

    // ===== Main loop: Phase C(t) fused with Phase A(t+G) =====
    for (int tile = tile0; tile < NTILES; tile += G) {
        const int node0 = tile * NT;
        const int nextt = tile + G;
        const bool have_next = nextt < NTILES;

        if (have_next) {
            #pragma unroll
            for (int t = 0; t < 4; ++t)
                #pragma unroll
                for (int r = 0; r < 4; ++r) accA[t][r] = 0.f;
        }

        #pragma unroll 1
        for (int kc = 0; kc < 4; ++kc) {
            __syncthreads();
            // stage C chunk (fp32) + A quarter (fp16 frags) in one window
            #pragma unroll
            for (int it = 0; it < 8; ++it) {
                int j = tid + it * THREADS;
                int k4 = j & 31, n = j >> 5;
                int node = node0 + n;
                float4 v = make_float4(0.f, 0.f, 0.f, 0.f);
                if (node < N_NODES) v = *(const float4*)(x + (size_t)node * F_DIM + kc * 128 + k4 * 4);
                xs4[k4 * 128 + (n ^ (k4 & 7))] = v;
            }
            if (have_next) stage_A(smc, x, nextt * NT, kc, tid);
            __syncthreads();

            // fused compute: 8 blocks of 16 C-iterations, one A ks-slice per block
            const ulonglong2* xcol = (const ulonglong2*)xs4 + f4 * 128;
            const int sw = f4 & 7;
            #pragma unroll
            for (int nb = 0; nb < 8; ++nb) {
                if (have_next) mma_A_step(smc, accA, nb, kc, nt, chalf, lane);
                #pragma unroll
                for (int ni = 0; ni < 16; ++ni) {
                    int n = nb * 16 + ni;
                    float4 sv = ss4[n * 16 + (w ^ (n & 15))];   // warp-uniform broadcast
                    ulonglong2 xv = xcol[n ^ sw];
                    ull t0 = pack2(sv.x, sv.x), t1 = pack2(sv.y, sv.y);
                    ull t2 = pack2(sv.z, sv.z), t3 = pack2(sv.w, sv.w);
                    Macc[kc][0][0] = fma2(xv.x, t0, Macc[kc][0][0]);
                    Macc[kc][0][1] = fma2(xv.y, t0, Macc[kc][0][1]);
                    Macc[kc][1][0] = fma2(xv.x, t1, Macc[kc][1][0]);
                    Macc[kc][1][1] = fma2(xv.y, t1, Macc[kc][1][1]);
                    Macc[kc][2][0] = fma2(xv.x, t2, Macc[kc][2][0]);
                    Macc[kc][2][1] = fma2(xv.y, t2, Macc[kc][2][1]);
                    Macc[kc][3][0] = fma2(xv.x, t3, Macc[kc][3][0]);
                    Macc[kc][3][1] = fma2(xv.y, t3, Macc[kc][3][1]);
                }
            }
        }

        if (have_next) {
            __syncthreads();       // all warps done with s(tile); S reusable
            {
                const int r0 = nt * 16 + (lane >> 2);
                const int r1 = r0 + 8;
                #pragma unroll
                for (int t = 0; t < 4; ++t) {
                    int c = chalf * 32 + t * 8 + (lane & 3) * 2;
                    int c4 = c >> 2, ci = c & 3;
                    float* p0 = sSf + r0 * 64 + (c4 ^ (r0 & 15)) * 4 + ci;
                    float* p1 = sSf + r1 * 64 + (c4 ^ (r1 & 15)) * 4 + ci;
                    p0[0] = accA[t][0]; p0[1] = accA[t][1];
                    p1[0] = accA[t][2]; p1[1] = accA[t][3];
                }
            }
            __syncthreads();
            #pragma unroll
            for (int i = 0; i < 4; ++i) {
                const int n = ng * 4 + i;
                float4 lv = ss4[n * 16 + (cq ^ (n & 15))];
                float l0 = lv.x + bpS[cq * 4 + 0];
                float l1 = lv.y + bpS[cq * 4 + 1];
                float l2 = lv.z + bpS[cq * 4 + 2];
                float l3 = lv.w + bpS[cq * 4 + 3];
                float m = fmaxf(fmaxf(l0, l1), fmaxf(l2, l3));
                #pragma unroll
                for (int d = 1; d < 16; d <<= 1) m = fmaxf(m, __shfl_xor_sync(0xffffffffu, m, d));
                float e0 = __expf(l0 - m), e1 = __expf(l1 - m), e2 = __expf(l2 - m), e3 = __expf(l3 - m);
                float s = e0 + e1 + e2 + e3;
                #pragma unroll
                for (int d = 1; d < 16; d <<= 1) s += __shfl_xor_sync(0xffffffffu, s, d);
                float r = __frcp_rn(s);
                if (nextt * NT + n >= N_NODES) r = 0.f;
                float4 sv = make_float4(e0 * r, e1 * r, e2 * r, e3 * r);
                cs0 += sv.x; cs1 += sv.y; cs2 += sv.z; cs3 += sv.w;
                ss4[n * 16 + (cq ^ (n & 15))] = sv;
            }
        }
    }

    // ---- per-block partial M ----
    #pragma unroll
    for (int kc = 0; kc < 4; ++kc)
        #pragma unroll
        for (int cc = 0; cc < 4; ++cc) {
            float a, b, c2, d;
            unpack2(Macc[kc][cc][0], a, b);
            unpack2(Macc[kc][cc][1], c2, d);
            int c = w * 4 + cc;
            int f = kc * 128 + f4 * 4;
            *(float4*)(g_Mpart + (size_t)blockIdx.x * (C_DIM * F_DIM) + c * F_DIM + f) =
                make_float4(a, b, c2, d);
        }
    // ---- per-block partial colsum(s) (scratch in dead s region) ----
    {
        float* csS = (float*)(smc + OFF_S);
        __syncthreads();
        if (tid < 64) csS[tid] = 0.f;
        __syncthreads();
        atomicAdd(&csS[cq * 4 + 0], cs0);
        atomicAdd(&csS[cq * 4 + 1], cs1);
        atomicAdd(&csS[cq * 4 + 2], cs2);
        atomicAdd(&csS[cq * 4 + 3], cs3);
        __syncthreads();
        if (tid < 64) g_cspart[blockIdx.x * 64 + tid] = csS[tid];
    }

    // ================= In-kernel epilogue (grid-synchronized) =================
    grid_sync();

    {
        unsigned idx = blockIdx.x * (unsigned)THREADS + (unsigned)tid;
        if (idx < C_DIM * F_DIM) {
            float s = 0.f;
            #pragma unroll 4
            for (int b = 0; b < G; ++b) s += g_Mpart[(size_t)b * (C_DIM * F_DIM) + idx];
            g_M[idx] = s;
        }
        if (blockIdx.x == 64 && tid < C_DIM) {
            float s = 0.f;
            #pragma unroll 4
            for (int b = 0; b < G; ++b) s += g_cspart[b * C_DIM + tid];
            g_cs[tid] = s;
        }
    }

    grid_sync();

    // pooled = M @ We + cs (x) be : blocks 0..15, 4 clusters each, f = tid
    if (blockIdx.x < 16) {
        const int f = tid;
        const int cb = blockIdx.x * 4;
        const float bef = be[f];
        float a0 = g_cs[cb + 0] * bef;
        float a1 = g_cs[cb + 1] * bef;
        float a2 = g_cs[cb + 2] * bef;
        float a3 = g_cs[cb + 3] * bef;
        #pragma unroll 8
        for (int k = 0; k < F_DIM; ++k) {
            float wv = We[(size_t)k * F_DIM + f];
            a0 += g_M[(cb + 0) * F_DIM + k] * wv;
            a1 += g_M[(cb + 1) * F_DIM + k] * wv;
            a2 += g_M[(cb + 2) * F_DIM + k] * wv;
            a3 += g_M[(cb + 3) * F_DIM + k] * wv;
        }
        g_pooled[(cb + 0) * F_DIM + f] = a0;
        g_pooled[(cb + 1) * F_DIM + f] = a1;
        g_pooled[(cb + 2) * F_DIM + f] = a2;
        g_pooled[(cb + 3) * F_DIM + f] = a3;
    }

    grid_sync();

    // out = pooled @ Wo + bo : blocks 0..63 (one cluster each), k split 2 ways
    if (blockIdx.x < 64) {
        const int o = tid & 255, q = tid >> 8, c = blockIdx.x;
        float a = 0.f;
        const int kbeg = q * 256;
        #pragma unroll 8
        for (int k = kbeg; k < kbeg + 256; ++k)
            a += g_pooled[c * F_DIM + k] * Wo[(size_t)k * O_DIM + o];
        float* rsm = (float*)(smc + OFF_XC);
        rsm[q * 256 + o] = a;
        __syncthreads();
        if (q == 0) out[c * O_DIM + o] = rsm[o] + rsm[256 + o] + bo[o];
    }
}

extern "C" void kernel_launch(void* const* d_in, const int* in_sizes, int n_in,
                              void* d_out, int out_size) {
    const float* x  = (const float*)d_in[0];
    // d_in[1] = edge_index (int64), d_in[2] = batch (int64): unused by the output
    const float* Wp = (const float*)d_in[3];
    const float* bp = (const float*)d_in[4];
    const float* We = (const float*)d_in[5];
    const float* be = (const float*)d_in[6];
    const float* Wo = (const float*)d_in[7];
    const float* bo = (const float*)d_in[8];
    float* out = (float*)d_out;

    int dev = 0;
    cudaGetDevice(&dev);
    int smc_n = GRID_MAX;
    cudaDeviceGetAttribute(&smc_n, cudaDevAttrMultiProcessorCount, dev);
    int G = smc_n < GRID_MAX ? smc_n : GRID_MAX;

    cudaFuncSetAttribute(k1_fused, cudaFuncAttributeMaxDynamicSharedMemorySize, SMEM_TOTAL);
    k1_fused<<<G, THREADS, SMEM_TOTAL>>>(x, Wp, bp, We, be, Wo, bo, out);
}